// round 1
// baseline (speedup 1.0000x reference)
#include <cuda_runtime.h>
#include <math.h>

// Problem constants
#define BB 2
#define NN 2048
#define DD 512
#define HH 8
#define DHH 64
#define PP 64

// Scratch (no cudaMalloc allowed): q,k,v in [B,H,N,DH], att in [B,N,H*DH]
__device__ float g_q[BB * HH * NN * DHH];
__device__ float g_k[BB * HH * NN * DHH];
__device__ float g_v[BB * HH * NN * DHH];
__device__ float g_att[BB * NN * HH * DHH];

// ---------------------------------------------------------------------------
// Kernel 1: QKV projection. X[4096,512] @ W[512,512] -> [B,H,N,DH] layout.
// 64x64 tile, BK=16, 256 threads, 4x4 register tile per thread.
// blockIdx.z selects Wq/Wk/Wv and output buffer.
// ---------------------------------------------------------------------------
__global__ __launch_bounds__(256) void qkv_gemm(
    const float* __restrict__ x,
    const float* __restrict__ Wq,
    const float* __restrict__ Wk,
    const float* __restrict__ Wv)
{
    const float* W = (blockIdx.z == 0) ? Wq : ((blockIdx.z == 1) ? Wk : Wv);
    float* out = (blockIdx.z == 0) ? g_q : ((blockIdx.z == 1) ? g_k : g_v);

    __shared__ float As[64][17];   // [m][k], padded
    __shared__ float Bs[16][64];   // [k][n]

    const int tx = threadIdx.x;    // 0..15
    const int ty = threadIdx.y;    // 0..15
    const int tid = ty * 16 + tx;

    const int rowBase = blockIdx.y * 64;
    const int colBase = blockIdx.x * 64;

    const int lr = tid >> 2;            // A-load row 0..63
    const int lc = (tid & 3) << 2;      // A-load col group
    const int kr = tid >> 4;            // B-load row 0..15
    const int kc = (tid & 15) << 2;     // B-load col group

    float acc[4][4] = {};

    for (int kt = 0; kt < DD; kt += 16) {
        float4 av = *(const float4*)&x[(rowBase + lr) * DD + kt + lc];
        As[lr][lc + 0] = av.x; As[lr][lc + 1] = av.y;
        As[lr][lc + 2] = av.z; As[lr][lc + 3] = av.w;
        float4 bv = *(const float4*)&W[(kt + kr) * DD + colBase + kc];
        *(float4*)&Bs[kr][kc] = bv;
        __syncthreads();

        #pragma unroll
        for (int k = 0; k < 16; k++) {
            float a[4];
            #pragma unroll
            for (int i = 0; i < 4; i++) a[i] = As[ty * 4 + i][k];
            float4 b4 = *(float4*)&Bs[k][tx * 4];
            float b[4] = {b4.x, b4.y, b4.z, b4.w};
            #pragma unroll
            for (int i = 0; i < 4; i++)
                #pragma unroll
                for (int j = 0; j < 4; j++)
                    acc[i][j] = fmaf(a[i], b[j], acc[i][j]);
        }
        __syncthreads();
    }

    // Epilogue: (row=bn, col=h*64+dh) -> [b][h][n][dh]
    #pragma unroll
    for (int i = 0; i < 4; i++) {
        int gm = rowBase + ty * 4 + i;
        int b = gm >> 11;          // / NN
        int n = gm & (NN - 1);
        #pragma unroll
        for (int j = 0; j < 4; j++) {
            int gn = colBase + tx * 4 + j;
            int h = gn >> 6;
            int dh = gn & 63;
            out[(((b * HH + h) * NN) + n) * DHH + dh] = acc[i][j];
        }
    }
}

// ---------------------------------------------------------------------------
// Kernel 2: flash attention per (b, h, 64-query tile), fp32 online softmax.
//   sim = (q.k + rel_pos[clip(j-i)+P, h]) * scale
//   attn = softmax(sim) * c_emb[clip(j-i)+P, h]   (gate AFTER softmax)
//   out  = attn @ v
// Thread mapping: 256 threads = 16 row-groups x 16 col-groups, 4x4 per thread.
// ---------------------------------------------------------------------------
#define ATT_SMEM_FLOATS (4 * 64 * 65 + 132 + 132)

__global__ __launch_bounds__(256) void attention_kernel(
    const float* __restrict__ rel_pos,
    const float* __restrict__ c_emb)
{
    extern __shared__ float sm[];
    float* Qs   = sm;                 // [64][65]
    float* Ks   = Qs + 64 * 65;       // [64][65]
    float* Vs   = Ks + 64 * 65;       // [64][65]
    float* Ps   = Vs + 64 * 65;       // [64][65]
    float* relS = Ps + 64 * 65;       // [129] (pad 132)
    float* gateS= relS + 132;         // [129]

    const int qb  = blockIdx.x;       // 0..31
    const int h   = blockIdx.y;       // 0..7
    const int b   = blockIdx.z;       // 0..1
    const int tid = threadIdx.x;      // 0..255
    const int rg  = tid >> 4;         // 0..15 (row group: rows rg*4..rg*4+3)
    const int cg  = tid & 15;         // 0..15 (col group: cols cg*4..cg*4+3)

    const float* qptr = g_q + (size_t)((b * HH + h) * NN) * DHH;
    const float* kptr = g_k + (size_t)((b * HH + h) * NN) * DHH;
    const float* vptr = g_v + (size_t)((b * HH + h) * NN) * DHH;

    const int qbase = qb * 64;

    // Load Q tile (64x64) as float4
    for (int t = tid; t < 1024; t += 256) {
        int row = t >> 4, c4 = (t & 15) << 2;
        float4 v4 = *(const float4*)&qptr[(qbase + row) * DHH + c4];
        Qs[row * 65 + c4 + 0] = v4.x; Qs[row * 65 + c4 + 1] = v4.y;
        Qs[row * 65 + c4 + 2] = v4.z; Qs[row * 65 + c4 + 3] = v4.w;
    }
    // Per-head bias / gate tables (129 entries each)
    for (int t = tid; t < 129; t += 256) {
        relS[t]  = rel_pos[t * HH + h];
        gateS[t] = c_emb[t * HH + h];
    }
    __syncthreads();

    float m[4], l[4], o[4][4];
    #pragma unroll
    for (int i = 0; i < 4; i++) {
        m[i] = -1e30f; l[i] = 0.f;
        #pragma unroll
        for (int j = 0; j < 4; j++) o[i][j] = 0.f;
    }
    const float scale = 0.125f;  // DH^-0.5

    for (int kb = 0; kb < NN; kb += 64) {
        __syncthreads();  // protect Ks/Vs/Ps from prior iteration
        // Load K and V tiles
        for (int t = tid; t < 1024; t += 256) {
            int row = t >> 4, c4 = (t & 15) << 2;
            float4 kv = *(const float4*)&kptr[(kb + row) * DHH + c4];
            Ks[row * 65 + c4 + 0] = kv.x; Ks[row * 65 + c4 + 1] = kv.y;
            Ks[row * 65 + c4 + 2] = kv.z; Ks[row * 65 + c4 + 3] = kv.w;
            float4 vv = *(const float4*)&vptr[(kb + row) * DHH + c4];
            Vs[row * 65 + c4 + 0] = vv.x; Vs[row * 65 + c4 + 1] = vv.y;
            Vs[row * 65 + c4 + 2] = vv.z; Vs[row * 65 + c4 + 3] = vv.w;
        }
        __syncthreads();

        // S = Q K^T (4x4 per thread)
        float s[4][4] = {};
        #pragma unroll 4
        for (int d = 0; d < 64; d++) {
            float a[4], kvv[4];
            #pragma unroll
            for (int i = 0; i < 4; i++) a[i] = Qs[(rg * 4 + i) * 65 + d];
            #pragma unroll
            for (int j = 0; j < 4; j++) kvv[j] = Ks[(cg * 4 + j) * 65 + d];
            #pragma unroll
            for (int i = 0; i < 4; i++)
                #pragma unroll
                for (int j = 0; j < 4; j++)
                    s[i][j] = fmaf(a[i], kvv[j], s[i][j]);
        }

        // bias + scale, online softmax, gated P written to smem
        float corr[4];
        #pragma unroll
        for (int i = 0; i < 4; i++) {
            int ig = qbase + rg * 4 + i;
            float mx = -1e30f;
            float sv[4];
            #pragma unroll
            for (int j = 0; j < 4; j++) {
                int jg = kb + cg * 4 + j;
                int d = jg - ig;
                d = (d < -PP) ? -PP : ((d > PP) ? PP : d);
                int idx = d + PP;
                sv[j] = (s[i][j] + relS[idx]) * scale;
                s[i][j] = (float)idx;   // stash idx for gate lookup
                mx = fmaxf(mx, sv[j]);
            }
            // row max over 16 col-group lanes (lanes stay within 16-lane half)
            #pragma unroll
            for (int off = 8; off >= 1; off >>= 1)
                mx = fmaxf(mx, __shfl_xor_sync(0xffffffffu, mx, off));
            float mnew = fmaxf(m[i], mx);
            corr[i] = __expf(m[i] - mnew);
            float rowsum = 0.f;
            #pragma unroll
            for (int j = 0; j < 4; j++) {
                float p = __expf(sv[j] - mnew);
                rowsum += p;
                int idx = (int)s[i][j];
                Ps[(rg * 4 + i) * 65 + cg * 4 + j] = p * gateS[idx];
            }
            #pragma unroll
            for (int off = 8; off >= 1; off >>= 1)
                rowsum += __shfl_xor_sync(0xffffffffu, rowsum, off);
            l[i] = l[i] * corr[i] + rowsum;
            m[i] = mnew;
        }
        // rescale accumulator
        #pragma unroll
        for (int i = 0; i < 4; i++)
            #pragma unroll
            for (int j = 0; j < 4; j++)
                o[i][j] *= corr[i];
        __syncthreads();

        // O += P V (P gated), cols of thread = dims cg*4..cg*4+3
        #pragma unroll 4
        for (int j = 0; j < 64; j++) {
            float pv[4], vv[4];
            #pragma unroll
            for (int i = 0; i < 4; i++) pv[i] = Ps[(rg * 4 + i) * 65 + j];
            #pragma unroll
            for (int jd = 0; jd < 4; jd++) vv[jd] = Vs[j * 65 + cg * 4 + jd];
            #pragma unroll
            for (int i = 0; i < 4; i++)
                #pragma unroll
                for (int jd = 0; jd < 4; jd++)
                    o[i][jd] = fmaf(pv[i], vv[jd], o[i][jd]);
        }
    }

    // Finalize: divide by denominator, write [b][n][h*64+dh]
    #pragma unroll
    for (int i = 0; i < 4; i++) {
        int ig = qbase + rg * 4 + i;
        float inv = 1.f / l[i];
        float4 ov;
        ov.x = o[i][0] * inv; ov.y = o[i][1] * inv;
        ov.z = o[i][2] * inv; ov.w = o[i][3] * inv;
        *(float4*)&g_att[(size_t)((b * NN + ig) * HH + h) * DHH + cg * 4] = ov;
    }
}

// ---------------------------------------------------------------------------
// Kernel 3: output projection. g_att[4096,512] @ Wo[512,512] + bo -> d_out.
// ---------------------------------------------------------------------------
__global__ __launch_bounds__(256) void out_gemm(
    const float* __restrict__ Wo,
    const float* __restrict__ bo,
    float* __restrict__ y)
{
    __shared__ float As[64][17];
    __shared__ float Bs[16][64];

    const int tx = threadIdx.x;
    const int ty = threadIdx.y;
    const int tid = ty * 16 + tx;

    const int rowBase = blockIdx.y * 64;
    const int colBase = blockIdx.x * 64;

    const int lr = tid >> 2;
    const int lc = (tid & 3) << 2;
    const int kr = tid >> 4;
    const int kc = (tid & 15) << 2;

    float acc[4][4] = {};

    for (int kt = 0; kt < DD; kt += 16) {
        float4 av = *(const float4*)&g_att[(size_t)(rowBase + lr) * DD + kt + lc];
        As[lr][lc + 0] = av.x; As[lr][lc + 1] = av.y;
        As[lr][lc + 2] = av.z; As[lr][lc + 3] = av.w;
        float4 bv = *(const float4*)&Wo[(kt + kr) * DD + colBase + kc];
        *(float4*)&Bs[kr][kc] = bv;
        __syncthreads();

        #pragma unroll
        for (int k = 0; k < 16; k++) {
            float a[4];
            #pragma unroll
            for (int i = 0; i < 4; i++) a[i] = As[ty * 4 + i][k];
            float4 b4 = *(float4*)&Bs[k][tx * 4];
            float b[4] = {b4.x, b4.y, b4.z, b4.w};
            #pragma unroll
            for (int i = 0; i < 4; i++)
                #pragma unroll
                for (int j = 0; j < 4; j++)
                    acc[i][j] = fmaf(a[i], b[j], acc[i][j]);
        }
        __syncthreads();
    }

    #pragma unroll
    for (int i = 0; i < 4; i++) {
        int gm = rowBase + ty * 4 + i;
        #pragma unroll
        for (int j = 0; j < 4; j++) {
            int gn = colBase + tx * 4 + j;
            y[(size_t)gm * DD + gn] = acc[i][j] + bo[gn];
        }
    }
}

// ---------------------------------------------------------------------------
extern "C" void kernel_launch(void* const* d_in, const int* in_sizes, int n_in,
                              void* d_out, int out_size)
{
    const float* x       = (const float*)d_in[0];
    const float* Wq      = (const float*)d_in[1];
    const float* Wk      = (const float*)d_in[2];
    const float* Wv      = (const float*)d_in[3];
    const float* rel_pos = (const float*)d_in[4];
    const float* c_emb   = (const float*)d_in[5];
    const float* Wo      = (const float*)d_in[6];
    const float* bo      = (const float*)d_in[7];
    float* y             = (float*)d_out;

    // QKV projections: [4096,512] x [512,512] x3
    dim3 gQKV(DD / 64, (BB * NN) / 64, 3);
    dim3 tGemm(16, 16);
    qkv_gemm<<<gQKV, tGemm>>>(x, Wq, Wk, Wv);

    // Attention
    size_t attSmem = (size_t)ATT_SMEM_FLOATS * sizeof(float);
    cudaFuncSetAttribute(attention_kernel,
                         cudaFuncAttributeMaxDynamicSharedMemorySize,
                         (int)attSmem);
    dim3 gAtt(NN / 64, HH, BB);
    attention_kernel<<<gAtt, 256, attSmem>>>(rel_pos, c_emb);

    // Output projection
    dim3 gOut(DD / 64, (BB * NN) / 64);
    out_gemm<<<gOut, tGemm>>>(Wo, bo, y);
}

// round 2
// speedup vs baseline: 1.2974x; 1.2974x over previous
#include <cuda_runtime.h>
#include <math.h>

// Problem constants
#define BB 2
#define NN 2048
#define DD 512
#define HH 8
#define DHH 64
#define PP 64

// Scratch: q,k,v in [B,H,N,DH], att in [B,N,H*DH]
__device__ float g_q[BB * HH * NN * DHH];
__device__ float g_k[BB * HH * NN * DHH];
__device__ float g_v[BB * HH * NN * DHH];
__device__ float g_att[BB * NN * HH * DHH];

// ---------------------------------------------------------------------------
// mma.sync m16n8k8 tf32 helpers
// ---------------------------------------------------------------------------
__device__ __forceinline__ unsigned f2tf(float x) {
    unsigned r;
    asm("cvt.rna.tf32.f32 %0, %1;" : "=r"(r) : "f"(x));
    return r;
}
__device__ __forceinline__ float ex2f(float x) {
    float r;
    asm("ex2.approx.f32 %0, %1;" : "=f"(r) : "f"(x));
    return r;
}
__device__ __forceinline__ void mma8(float c[4], const unsigned a[4], const unsigned b[2]) {
    asm volatile(
        "mma.sync.aligned.m16n8k8.row.col.f32.tf32.tf32.f32 "
        "{%0,%1,%2,%3}, {%4,%5,%6,%7}, {%8,%9}, {%0,%1,%2,%3};\n"
        : "+f"(c[0]), "+f"(c[1]), "+f"(c[2]), "+f"(c[3])
        : "r"(a[0]), "r"(a[1]), "r"(a[2]), "r"(a[3]), "r"(b[0]), "r"(b[1]));
}

// ---------------------------------------------------------------------------
// Kernel 1: QKV projection (SIMT fp32, verified in R1)
// ---------------------------------------------------------------------------
__global__ __launch_bounds__(256) void qkv_gemm(
    const float* __restrict__ x,
    const float* __restrict__ Wq,
    const float* __restrict__ Wk,
    const float* __restrict__ Wv)
{
    const float* W = (blockIdx.z == 0) ? Wq : ((blockIdx.z == 1) ? Wk : Wv);
    float* out = (blockIdx.z == 0) ? g_q : ((blockIdx.z == 1) ? g_k : g_v);

    __shared__ float As[64][17];
    __shared__ float Bs[16][64];

    const int tx = threadIdx.x;
    const int ty = threadIdx.y;
    const int tid = ty * 16 + tx;

    const int rowBase = blockIdx.y * 64;
    const int colBase = blockIdx.x * 64;

    const int lr = tid >> 2;
    const int lc = (tid & 3) << 2;
    const int kr = tid >> 4;
    const int kc = (tid & 15) << 2;

    float acc[4][4] = {};

    for (int kt = 0; kt < DD; kt += 16) {
        float4 av = *(const float4*)&x[(rowBase + lr) * DD + kt + lc];
        As[lr][lc + 0] = av.x; As[lr][lc + 1] = av.y;
        As[lr][lc + 2] = av.z; As[lr][lc + 3] = av.w;
        float4 bv = *(const float4*)&W[(kt + kr) * DD + colBase + kc];
        *(float4*)&Bs[kr][kc] = bv;
        __syncthreads();

        #pragma unroll
        for (int k = 0; k < 16; k++) {
            float a[4];
            #pragma unroll
            for (int i = 0; i < 4; i++) a[i] = As[ty * 4 + i][k];
            float4 b4 = *(float4*)&Bs[k][tx * 4];
            float b[4] = {b4.x, b4.y, b4.z, b4.w};
            #pragma unroll
            for (int i = 0; i < 4; i++)
                #pragma unroll
                for (int j = 0; j < 4; j++)
                    acc[i][j] = fmaf(a[i], b[j], acc[i][j]);
        }
        __syncthreads();
    }

    #pragma unroll
    for (int i = 0; i < 4; i++) {
        int gm = rowBase + ty * 4 + i;
        int b = gm >> 11;
        int n = gm & (NN - 1);
        #pragma unroll
        for (int j = 0; j < 4; j++) {
            int gn = colBase + tx * 4 + j;
            int h = gn >> 6;
            int dh = gn & 63;
            out[(((b * HH + h) * NN) + n) * DHH + dh] = acc[i][j];
        }
    }
}

// ---------------------------------------------------------------------------
// Kernel 2: flash attention with mma.sync tf32.
// CTA = (b, h, 64-query tile). 4 warps, each owns 16 query rows.
// Q (pre-scaled by 0.125*log2e, tf32-rounded) lives in registers.
// Softmax in exp2 domain: identical result to base-e softmax.
// Gate applied to numerator only (matches reference: softmax then gate).
// ---------------------------------------------------------------------------
#define KS_STRIDE 68   // bank = 4g+t : conflict-free B-frag loads for K
#define VS_STRIDE 72   // bank = 8t+g : conflict-free B-frag loads for V
#define PS_STRIDE 68   // bank = 4g+t : conflict-free A-frag loads for P

#define ATT_SMEM_FLOATS (64*KS_STRIDE + 64*VS_STRIDE + 64*PS_STRIDE + 132 + 132)

__global__ __launch_bounds__(128) void attention_mma(
    const float* __restrict__ rel_pos,
    const float* __restrict__ c_emb)
{
    extern __shared__ float sm[];
    float* Ks    = sm;                        // [64][68]
    float* Vs    = Ks + 64 * KS_STRIDE;       // [64][72]
    float* Ps    = Vs + 64 * VS_STRIDE;       // [64][68]
    float* relS  = Ps + 64 * PS_STRIDE;       // [129] pre-scaled
    float* gateS = relS + 132;                // [129]

    const int qb  = blockIdx.x;
    const int h   = blockIdx.y;
    const int b   = blockIdx.z;
    const int tid = threadIdx.x;
    const int w    = tid >> 5;
    const int lane = tid & 31;
    const int g    = lane >> 2;   // groupID
    const int t    = lane & 3;    // threadID in group

    const float* qptr = g_q + (size_t)((b * HH + h) * NN) * DHH;
    const float* kptr = g_k + (size_t)((b * HH + h) * NN) * DHH;
    const float* vptr = g_v + (size_t)((b * HH + h) * NN) * DHH;

    const int qbase = qb * 64;
    const int i0 = qbase + w * 16;

    // log2(e) * DH^-0.5
    const float sc = 0.125f * 1.4426950408889634f;

    for (int u = tid; u < 129; u += 128) {
        relS[u]  = rel_pos[u * HH + h] * sc;
        gateS[u] = c_emb[u * HH + h];
    }

    // Q fragments (A operand), in registers for all key blocks
    unsigned qa[8][4];
    #pragma unroll
    for (int kc = 0; kc < 8; kc++) {
        qa[kc][0] = f2tf(qptr[(i0 + g)     * DHH + kc * 8 + t]     * sc);
        qa[kc][1] = f2tf(qptr[(i0 + g + 8) * DHH + kc * 8 + t]     * sc);
        qa[kc][2] = f2tf(qptr[(i0 + g)     * DHH + kc * 8 + t + 4] * sc);
        qa[kc][3] = f2tf(qptr[(i0 + g + 8) * DHH + kc * 8 + t + 4] * sc);
    }

    float m0 = -1e30f, m1 = -1e30f, l0 = 0.f, l1 = 0.f;
    float o[8][4];
    #pragma unroll
    for (int nt = 0; nt < 8; nt++)
        #pragma unroll
        for (int j = 0; j < 4; j++) o[nt][j] = 0.f;

    for (int kb = 0; kb < NN; kb += 64) {
        __syncthreads();   // prior iter done reading Ks/Vs
        // Fill K, V tiles (coalesced float4)
        #pragma unroll
        for (int r8 = 0; r8 < 8; r8++) {
            int row = r8 * 8 + (tid >> 4);
            int c4  = (tid & 15) << 2;
            float4 kv = *(const float4*)&kptr[(size_t)(kb + row) * DHH + c4];
            Ks[row * KS_STRIDE + c4 + 0] = kv.x;
            Ks[row * KS_STRIDE + c4 + 1] = kv.y;
            Ks[row * KS_STRIDE + c4 + 2] = kv.z;
            Ks[row * KS_STRIDE + c4 + 3] = kv.w;
            float4 vv = *(const float4*)&vptr[(size_t)(kb + row) * DHH + c4];
            Vs[row * VS_STRIDE + c4 + 0] = vv.x;
            Vs[row * VS_STRIDE + c4 + 1] = vv.y;
            Vs[row * VS_STRIDE + c4 + 2] = vv.z;
            Vs[row * VS_STRIDE + c4 + 3] = vv.w;
        }
        __syncthreads();

        // S = Q K^T  (scaled by sc already via Q)
        float s[8][4];
        #pragma unroll
        for (int nt = 0; nt < 8; nt++) {
            float c[4] = {0.f, 0.f, 0.f, 0.f};
            #pragma unroll
            for (int kc = 0; kc < 8; kc++) {
                unsigned bb[2];
                bb[0] = __float_as_uint(Ks[(nt * 8 + g) * KS_STRIDE + kc * 8 + t]);
                bb[1] = __float_as_uint(Ks[(nt * 8 + g) * KS_STRIDE + kc * 8 + t + 4]);
                mma8(c, qa[kc], bb);
            }
            s[nt][0] = c[0]; s[nt][1] = c[1]; s[nt][2] = c[2]; s[nt][3] = c[3];
        }

        // Bias add + online softmax
        const bool farhi = (kb >= qbase + 128);
        const bool farlo = (kb + 128 <= qbase);
        const bool far = farhi || farlo;
        const float cb = farhi ? relS[128]  : relS[0];
        const float cg = farhi ? gateS[128] : gateS[0];

        float mx0 = -1e30f, mx1 = -1e30f;
        #pragma unroll
        for (int nt = 0; nt < 8; nt++) {
            if (far) {
                s[nt][0] += cb; s[nt][1] += cb; s[nt][2] += cb; s[nt][3] += cb;
            } else {
                int j0 = kb + nt * 8 + 2 * t;
                int d0 = j0 - (i0 + g);
                int d1 = d0 - 8;
                int i00 = min(max(d0,     -PP), PP) + PP;
                int i01 = min(max(d0 + 1, -PP), PP) + PP;
                int i10 = min(max(d1,     -PP), PP) + PP;
                int i11 = min(max(d1 + 1, -PP), PP) + PP;
                s[nt][0] += relS[i00]; s[nt][1] += relS[i01];
                s[nt][2] += relS[i10]; s[nt][3] += relS[i11];
            }
            mx0 = fmaxf(mx0, fmaxf(s[nt][0], s[nt][1]));
            mx1 = fmaxf(mx1, fmaxf(s[nt][2], s[nt][3]));
        }
        mx0 = fmaxf(mx0, __shfl_xor_sync(0xffffffffu, mx0, 1));
        mx0 = fmaxf(mx0, __shfl_xor_sync(0xffffffffu, mx0, 2));
        mx1 = fmaxf(mx1, __shfl_xor_sync(0xffffffffu, mx1, 1));
        mx1 = fmaxf(mx1, __shfl_xor_sync(0xffffffffu, mx1, 2));

        float mn0 = fmaxf(m0, mx0), mn1 = fmaxf(m1, mx1);
        float corr0 = ex2f(m0 - mn0), corr1 = ex2f(m1 - mn1);

        float rs0 = 0.f, rs1 = 0.f;
        const int prow0 = (w * 16 + g) * PS_STRIDE;
        const int prow1 = (w * 16 + g + 8) * PS_STRIDE;
        #pragma unroll
        for (int nt = 0; nt < 8; nt++) {
            float p00 = ex2f(s[nt][0] - mn0);
            float p01 = ex2f(s[nt][1] - mn0);
            float p10 = ex2f(s[nt][2] - mn1);
            float p11 = ex2f(s[nt][3] - mn1);
            rs0 += p00 + p01;
            rs1 += p10 + p11;
            float g00, g01, g10, g11;
            if (far) {
                g00 = g01 = g10 = g11 = cg;
            } else {
                int j0 = kb + nt * 8 + 2 * t;
                int d0 = j0 - (i0 + g);
                int d1 = d0 - 8;
                g00 = gateS[min(max(d0,     -PP), PP) + PP];
                g01 = gateS[min(max(d0 + 1, -PP), PP) + PP];
                g10 = gateS[min(max(d1,     -PP), PP) + PP];
                g11 = gateS[min(max(d1 + 1, -PP), PP) + PP];
            }
            float2 w0, w1;
            w0.x = __uint_as_float(f2tf(p00 * g00));
            w0.y = __uint_as_float(f2tf(p01 * g01));
            w1.x = __uint_as_float(f2tf(p10 * g10));
            w1.y = __uint_as_float(f2tf(p11 * g11));
            *(float2*)&Ps[prow0 + nt * 8 + 2 * t] = w0;
            *(float2*)&Ps[prow1 + nt * 8 + 2 * t] = w1;
        }
        rs0 += __shfl_xor_sync(0xffffffffu, rs0, 1);
        rs0 += __shfl_xor_sync(0xffffffffu, rs0, 2);
        rs1 += __shfl_xor_sync(0xffffffffu, rs1, 1);
        rs1 += __shfl_xor_sync(0xffffffffu, rs1, 2);

        l0 = l0 * corr0 + rs0; m0 = mn0;
        l1 = l1 * corr1 + rs1; m1 = mn1;

        #pragma unroll
        for (int nt = 0; nt < 8; nt++) {
            o[nt][0] *= corr0; o[nt][1] *= corr0;
            o[nt][2] *= corr1; o[nt][3] *= corr1;
        }

        __syncwarp();   // Ps rows are per-warp private: warp-level ordering suffices

        // O += P V
        #pragma unroll
        for (int kc = 0; kc < 8; kc++) {
            unsigned a[4];
            a[0] = __float_as_uint(Ps[prow0 + kc * 8 + t]);
            a[1] = __float_as_uint(Ps[prow1 + kc * 8 + t]);
            a[2] = __float_as_uint(Ps[prow0 + kc * 8 + t + 4]);
            a[3] = __float_as_uint(Ps[prow1 + kc * 8 + t + 4]);
            #pragma unroll
            for (int nt = 0; nt < 8; nt++) {
                unsigned bb[2];
                bb[0] = __float_as_uint(Vs[(kc * 8 + t)     * VS_STRIDE + nt * 8 + g]);
                bb[1] = __float_as_uint(Vs[(kc * 8 + t + 4) * VS_STRIDE + nt * 8 + g]);
                mma8(o[nt], a, bb);
            }
        }
    }

    // Finalize: divide by denominator, write [b][n][h*64+dh]
    float inv0 = 1.f / l0, inv1 = 1.f / l1;
    const size_t base = ((size_t)b * NN) * (HH * DHH) + h * DHH;
    const int r0 = i0 + g, r1 = i0 + g + 8;
    #pragma unroll
    for (int nt = 0; nt < 8; nt++) {
        float2 v0, v1;
        v0.x = o[nt][0] * inv0; v0.y = o[nt][1] * inv0;
        v1.x = o[nt][2] * inv1; v1.y = o[nt][3] * inv1;
        *(float2*)&g_att[base + (size_t)r0 * (HH * DHH) + nt * 8 + 2 * t] = v0;
        *(float2*)&g_att[base + (size_t)r1 * (HH * DHH) + nt * 8 + 2 * t] = v1;
    }
}

// ---------------------------------------------------------------------------
// Kernel 3: output projection (SIMT fp32, verified in R1)
// ---------------------------------------------------------------------------
__global__ __launch_bounds__(256) void out_gemm(
    const float* __restrict__ Wo,
    const float* __restrict__ bo,
    float* __restrict__ y)
{
    __shared__ float As[64][17];
    __shared__ float Bs[16][64];

    const int tx = threadIdx.x;
    const int ty = threadIdx.y;
    const int tid = ty * 16 + tx;

    const int rowBase = blockIdx.y * 64;
    const int colBase = blockIdx.x * 64;

    const int lr = tid >> 2;
    const int lc = (tid & 3) << 2;
    const int kr = tid >> 4;
    const int kc = (tid & 15) << 2;

    float acc[4][4] = {};

    for (int kt = 0; kt < DD; kt += 16) {
        float4 av = *(const float4*)&g_att[(size_t)(rowBase + lr) * DD + kt + lc];
        As[lr][lc + 0] = av.x; As[lr][lc + 1] = av.y;
        As[lr][lc + 2] = av.z; As[lr][lc + 3] = av.w;
        float4 bv = *(const float4*)&Wo[(kt + kr) * DD + colBase + kc];
        *(float4*)&Bs[kr][kc] = bv;
        __syncthreads();

        #pragma unroll
        for (int k = 0; k < 16; k++) {
            float a[4];
            #pragma unroll
            for (int i = 0; i < 4; i++) a[i] = As[ty * 4 + i][k];
            float4 b4 = *(float4*)&Bs[k][tx * 4];
            float b[4] = {b4.x, b4.y, b4.z, b4.w};
            #pragma unroll
            for (int i = 0; i < 4; i++)
                #pragma unroll
                for (int j = 0; j < 4; j++)
                    acc[i][j] = fmaf(a[i], b[j], acc[i][j]);
        }
        __syncthreads();
    }

    #pragma unroll
    for (int i = 0; i < 4; i++) {
        int gm = rowBase + ty * 4 + i;
        #pragma unroll
        for (int j = 0; j < 4; j++) {
            int gn = colBase + tx * 4 + j;
            y[(size_t)gm * DD + gn] = acc[i][j] + bo[gn];
        }
    }
}

// ---------------------------------------------------------------------------
extern "C" void kernel_launch(void* const* d_in, const int* in_sizes, int n_in,
                              void* d_out, int out_size)
{
    const float* x       = (const float*)d_in[0];
    const float* Wq      = (const float*)d_in[1];
    const float* Wk      = (const float*)d_in[2];
    const float* Wv      = (const float*)d_in[3];
    const float* rel_pos = (const float*)d_in[4];
    const float* c_emb   = (const float*)d_in[5];
    const float* Wo      = (const float*)d_in[6];
    const float* bo      = (const float*)d_in[7];
    float* y             = (float*)d_out;

    dim3 gQKV(DD / 64, (BB * NN) / 64, 3);
    dim3 tGemm(16, 16);
    qkv_gemm<<<gQKV, tGemm>>>(x, Wq, Wk, Wv);

    size_t attSmem = (size_t)ATT_SMEM_FLOATS * sizeof(float);
    cudaFuncSetAttribute(attention_mma,
                         cudaFuncAttributeMaxDynamicSharedMemorySize,
                         (int)attSmem);
    dim3 gAtt(NN / 64, HH, BB);
    attention_mma<<<gAtt, 128, attSmem>>>(rel_pos, c_emb);

    dim3 gOut(DD / 64, (BB * NN) / 64);
    out_gemm<<<gOut, tGemm>>>(Wo, bo, y);
}

// round 3
// speedup vs baseline: 3.5201x; 2.7133x over previous
#include <cuda_runtime.h>
#include <math.h>

// Problem constants
#define BB 2
#define NN 2048
#define DD 512
#define HH 8
#define DHH 64
#define PP 64

// Scratch: q,k,v in [B,H,N,DH], att in [B,N,H*DH]
__device__ float g_q[BB * HH * NN * DHH];
__device__ float g_k[BB * HH * NN * DHH];
__device__ float g_v[BB * HH * NN * DHH];
__device__ float g_att[BB * NN * HH * DHH];

// ---------------------------------------------------------------------------
// helpers
// ---------------------------------------------------------------------------
__device__ __forceinline__ unsigned f2tf(float x) {
    unsigned r;
    asm("cvt.rna.tf32.f32 %0, %1;" : "=r"(r) : "f"(x));
    return r;
}
__device__ __forceinline__ float f2tff(float x) {
    unsigned r;
    asm("cvt.rna.tf32.f32 %0, %1;" : "=r"(r) : "f"(x));
    return __uint_as_float(r);
}
__device__ __forceinline__ float ex2f(float x) {
    float r;
    asm("ex2.approx.f32 %0, %1;" : "=f"(r) : "f"(x));
    return r;
}
__device__ __forceinline__ void mma8(float c[4], const unsigned a[4], const unsigned b[2]) {
    asm volatile(
        "mma.sync.aligned.m16n8k8.row.col.f32.tf32.tf32.f32 "
        "{%0,%1,%2,%3}, {%4,%5,%6,%7}, {%8,%9}, {%0,%1,%2,%3};\n"
        : "+f"(c[0]), "+f"(c[1]), "+f"(c[2]), "+f"(c[3])
        : "r"(a[0]), "r"(a[1]), "r"(a[2]), "r"(a[3]), "r"(b[0]), "r"(b[1]));
}

// ---------------------------------------------------------------------------
// Kernel 1: QKV projection, tf32 mma. CTA: 128(m) x 64(n), 8 warps (4x2),
// warp tile 32x32 = 2 m-frags x 4 n-frags, K chunk 32.
// ---------------------------------------------------------------------------
#define AS_STRIDE 36
#define BS_STRIDE 36

__global__ __launch_bounds__(256) void qkv_mma(
    const float* __restrict__ x,
    const float* __restrict__ Wq,
    const float* __restrict__ Wk,
    const float* __restrict__ Wv)
{
    const float* W = (blockIdx.z == 0) ? Wq : ((blockIdx.z == 1) ? Wk : Wv);
    float* out = (blockIdx.z == 0) ? g_q : ((blockIdx.z == 1) ? g_k : g_v);

    __shared__ float As[128 * AS_STRIDE];  // [m][k] tf32-rounded
    __shared__ float Bs[64 * BS_STRIDE];   // [n][k] tf32-rounded (transposed W)

    const int tid = threadIdx.x;
    const int w = tid >> 5, lane = tid & 31;
    const int g = lane >> 2, t = lane & 3;
    const int wm = w >> 1, wn = w & 1;

    const int rowBase = blockIdx.y * 128;
    const int colBase = blockIdx.x * 64;

    float acc[2][4][4] = {};

    for (int kt = 0; kt < DD; kt += 32) {
        __syncthreads();
        // A tile: 128x32, float4 loads, rounded scalar stores
        #pragma unroll
        for (int i = 0; i < 4; i++) {
            int f = tid + i * 256;
            int row = f >> 3, c4 = (f & 7) << 2;
            float4 av = *(const float4*)&x[(size_t)(rowBase + row) * DD + kt + c4];
            As[row * AS_STRIDE + c4 + 0] = f2tff(av.x);
            As[row * AS_STRIDE + c4 + 1] = f2tff(av.y);
            As[row * AS_STRIDE + c4 + 2] = f2tff(av.z);
            As[row * AS_STRIDE + c4 + 3] = f2tff(av.w);
        }
        // B tile transposed: W[k][n] -> Bs[n][k], coalesced scalar loads
        #pragma unroll
        for (int i = 0; i < 8; i++) {
            int f = tid + i * 256;
            int k = f >> 6, n = f & 63;
            Bs[n * BS_STRIDE + k] = f2tff(W[(size_t)(kt + k) * DD + colBase + n]);
        }
        __syncthreads();

        #pragma unroll
        for (int ks = 0; ks < 4; ks++) {
            unsigned a[2][4];
            #pragma unroll
            for (int mi = 0; mi < 2; mi++) {
                int mb = wm * 32 + mi * 16;
                a[mi][0] = __float_as_uint(As[(mb + g)     * AS_STRIDE + ks * 8 + t]);
                a[mi][1] = __float_as_uint(As[(mb + g + 8) * AS_STRIDE + ks * 8 + t]);
                a[mi][2] = __float_as_uint(As[(mb + g)     * AS_STRIDE + ks * 8 + t + 4]);
                a[mi][3] = __float_as_uint(As[(mb + g + 8) * AS_STRIDE + ks * 8 + t + 4]);
            }
            #pragma unroll
            for (int ni = 0; ni < 4; ni++) {
                int n = wn * 32 + ni * 8 + g;
                unsigned bb[2];
                bb[0] = __float_as_uint(Bs[n * BS_STRIDE + ks * 8 + t]);
                bb[1] = __float_as_uint(Bs[n * BS_STRIDE + ks * 8 + t + 4]);
                mma8(acc[0][ni], a[0], bb);
                mma8(acc[1][ni], a[1], bb);
            }
        }
    }

    // Epilogue: scatter to [b][h][n][dh]
    #pragma unroll
    for (int mi = 0; mi < 2; mi++) {
        #pragma unroll
        for (int ni = 0; ni < 4; ni++) {
            int gm0 = rowBase + wm * 32 + mi * 16 + g;
            int gn  = colBase + wn * 32 + ni * 8 + 2 * t;
            int h = gn >> 6, dh = gn & 63;
            {
                int b = gm0 >> 11, n = gm0 & (NN - 1);
                float2 v; v.x = acc[mi][ni][0]; v.y = acc[mi][ni][1];
                *(float2*)&out[(size_t)(((b * HH + h) * NN) + n) * DHH + dh] = v;
            }
            {
                int gm1 = gm0 + 8;
                int b = gm1 >> 11, n = gm1 & (NN - 1);
                float2 v; v.x = acc[mi][ni][2]; v.y = acc[mi][ni][3];
                *(float2*)&out[(size_t)(((b * HH + h) * NN) + n) * DHH + dh] = v;
            }
        }
    }
}

// ---------------------------------------------------------------------------
// Kernel 2: flash attention, tf32 mma. CTA = (b, h, 128-query tile), 8 warps.
// K tile stored k-permuted so S-phase B-frags are one ld.shared.v2.
// ---------------------------------------------------------------------------
#define KS_STRIDE 68
#define VS_STRIDE 72
#define PS_STRIDE 68

#define ATT_SMEM_FLOATS (64*KS_STRIDE + 64*VS_STRIDE + 128*PS_STRIDE + 132 + 132)

__global__ __launch_bounds__(256) void attention_mma(
    const float* __restrict__ rel_pos,
    const float* __restrict__ c_emb)
{
    extern __shared__ float sm[];
    float* Ks    = sm;                        // [64][68] permuted k
    float* Vs    = Ks + 64 * KS_STRIDE;       // [64][72]
    float* Ps    = Vs + 64 * VS_STRIDE;       // [128][68]
    float* relS  = Ps + 128 * PS_STRIDE;      // [129] pre-scaled
    float* gateS = relS + 132;                // [129]

    const int qb  = blockIdx.x;
    const int h   = blockIdx.y;
    const int b   = blockIdx.z;
    const int tid = threadIdx.x;
    const int w    = tid >> 5;
    const int lane = tid & 31;
    const int g    = lane >> 2;
    const int t    = lane & 3;

    const float* qptr = g_q + (size_t)((b * HH + h) * NN) * DHH;
    const float* kptr = g_k + (size_t)((b * HH + h) * NN) * DHH;
    const float* vptr = g_v + (size_t)((b * HH + h) * NN) * DHH;

    const int i0 = qb * 128 + w * 16;

    const float sc = 0.125f * 1.4426950408889634f;  // log2(e)/8

    for (int u = tid; u < 129; u += 256) {
        relS[u]  = rel_pos[u * HH + h] * sc;
        gateS[u] = c_emb[u * HH + h];
    }

    // Q fragments in registers, pre-scaled + tf32-rounded
    unsigned qa[8][4];
    #pragma unroll
    for (int kc = 0; kc < 8; kc++) {
        qa[kc][0] = f2tf(qptr[(i0 + g)     * DHH + kc * 8 + t]     * sc);
        qa[kc][1] = f2tf(qptr[(i0 + g + 8) * DHH + kc * 8 + t]     * sc);
        qa[kc][2] = f2tf(qptr[(i0 + g)     * DHH + kc * 8 + t + 4] * sc);
        qa[kc][3] = f2tf(qptr[(i0 + g + 8) * DHH + kc * 8 + t + 4] * sc);
    }

    float m0 = -1e30f, m1 = -1e30f, l0 = 0.f, l1 = 0.f;
    float o[8][4];
    #pragma unroll
    for (int nt = 0; nt < 8; nt++)
        #pragma unroll
        for (int j = 0; j < 4; j++) o[nt][j] = 0.f;

    for (int kb = 0; kb < NN; kb += 64) {
        __syncthreads();
        // Fill K (permuted) and V tiles: 64 rows x 64 dims each
        #pragma unroll
        for (int r4 = 0; r4 < 4; r4++) {
            int row = r4 * 16 + (tid >> 4);
            int c4  = (tid & 15) << 2;
            float4 kv = *(const float4*)&kptr[(size_t)(kb + row) * DHH + c4];
            // perm: pos(k) = (k & ~7) | ((k&3)<<1) | ((k>>2)&1)
            int pbase = row * KS_STRIDE + (c4 & ~7) + ((c4 >> 2) & 1);
            Ks[pbase + 0] = kv.x;
            Ks[pbase + 2] = kv.y;
            Ks[pbase + 4] = kv.z;
            Ks[pbase + 6] = kv.w;
            float4 vv = *(const float4*)&vptr[(size_t)(kb + row) * DHH + c4];
            *(float4*)&Vs[row * VS_STRIDE + c4] = vv;
        }
        __syncthreads();

        // S = Q K^T
        float s[8][4];
        #pragma unroll
        for (int nt = 0; nt < 8; nt++) {
            float c[4] = {0.f, 0.f, 0.f, 0.f};
            #pragma unroll
            for (int kc = 0; kc < 8; kc++) {
                float2 kf = *(const float2*)&Ks[(nt * 8 + g) * KS_STRIDE + kc * 8 + 2 * t];
                unsigned bb[2];
                bb[0] = __float_as_uint(kf.x);
                bb[1] = __float_as_uint(kf.y);
                mma8(c, qa[kc], bb);
            }
            s[nt][0] = c[0]; s[nt][1] = c[1]; s[nt][2] = c[2]; s[nt][3] = c[3];
        }

        // Bias + online softmax (exp2 domain)
        const bool farhi = (kb >= i0 + 79);
        const bool farlo = (kb + 127 <= i0);
        const bool far = farhi || farlo;
        const float cb = farhi ? relS[128]  : relS[0];
        const float cg = farhi ? gateS[128] : gateS[0];

        float mx0 = -1e30f, mx1 = -1e30f;
        #pragma unroll
        for (int nt = 0; nt < 8; nt++) {
            if (far) {
                s[nt][0] += cb; s[nt][1] += cb; s[nt][2] += cb; s[nt][3] += cb;
            } else {
                int j0 = kb + nt * 8 + 2 * t;
                int d0 = j0 - (i0 + g);
                int d1 = d0 - 8;
                s[nt][0] += relS[min(max(d0,     -PP), PP) + PP];
                s[nt][1] += relS[min(max(d0 + 1, -PP), PP) + PP];
                s[nt][2] += relS[min(max(d1,     -PP), PP) + PP];
                s[nt][3] += relS[min(max(d1 + 1, -PP), PP) + PP];
            }
            mx0 = fmaxf(mx0, fmaxf(s[nt][0], s[nt][1]));
            mx1 = fmaxf(mx1, fmaxf(s[nt][2], s[nt][3]));
        }
        mx0 = fmaxf(mx0, __shfl_xor_sync(0xffffffffu, mx0, 1));
        mx0 = fmaxf(mx0, __shfl_xor_sync(0xffffffffu, mx0, 2));
        mx1 = fmaxf(mx1, __shfl_xor_sync(0xffffffffu, mx1, 1));
        mx1 = fmaxf(mx1, __shfl_xor_sync(0xffffffffu, mx1, 2));

        float mn0 = fmaxf(m0, mx0), mn1 = fmaxf(m1, mx1);
        float corr0 = ex2f(m0 - mn0), corr1 = ex2f(m1 - mn1);

        float rs0 = 0.f, rs1 = 0.f;
        const int prow0 = (w * 16 + g) * PS_STRIDE;
        const int prow1 = (w * 16 + g + 8) * PS_STRIDE;
        #pragma unroll
        for (int nt = 0; nt < 8; nt++) {
            float p00 = ex2f(s[nt][0] - mn0);
            float p01 = ex2f(s[nt][1] - mn0);
            float p10 = ex2f(s[nt][2] - mn1);
            float p11 = ex2f(s[nt][3] - mn1);
            rs0 += p00 + p01;
            rs1 += p10 + p11;
            float g00, g01, g10, g11;
            if (far) {
                g00 = g01 = g10 = g11 = cg;
            } else {
                int j0 = kb + nt * 8 + 2 * t;
                int d0 = j0 - (i0 + g);
                int d1 = d0 - 8;
                g00 = gateS[min(max(d0,     -PP), PP) + PP];
                g01 = gateS[min(max(d0 + 1, -PP), PP) + PP];
                g10 = gateS[min(max(d1,     -PP), PP) + PP];
                g11 = gateS[min(max(d1 + 1, -PP), PP) + PP];
            }
            float2 w0, w1;
            w0.x = __uint_as_float(f2tf(p00 * g00));
            w0.y = __uint_as_float(f2tf(p01 * g01));
            w1.x = __uint_as_float(f2tf(p10 * g10));
            w1.y = __uint_as_float(f2tf(p11 * g11));
            *(float2*)&Ps[prow0 + nt * 8 + 2 * t] = w0;
            *(float2*)&Ps[prow1 + nt * 8 + 2 * t] = w1;
        }
        rs0 += __shfl_xor_sync(0xffffffffu, rs0, 1);
        rs0 += __shfl_xor_sync(0xffffffffu, rs0, 2);
        rs1 += __shfl_xor_sync(0xffffffffu, rs1, 1);
        rs1 += __shfl_xor_sync(0xffffffffu, rs1, 2);

        l0 = l0 * corr0 + rs0; m0 = mn0;
        l1 = l1 * corr1 + rs1; m1 = mn1;

        #pragma unroll
        for (int nt = 0; nt < 8; nt++) {
            o[nt][0] *= corr0; o[nt][1] *= corr0;
            o[nt][2] *= corr1; o[nt][3] *= corr1;
        }

        __syncwarp();  // Ps rows are per-warp private

        // O += P V
        #pragma unroll
        for (int kc = 0; kc < 8; kc++) {
            unsigned a[4];
            a[0] = __float_as_uint(Ps[prow0 + kc * 8 + t]);
            a[1] = __float_as_uint(Ps[prow1 + kc * 8 + t]);
            a[2] = __float_as_uint(Ps[prow0 + kc * 8 + t + 4]);
            a[3] = __float_as_uint(Ps[prow1 + kc * 8 + t + 4]);
            #pragma unroll
            for (int nt = 0; nt < 8; nt++) {
                unsigned bb[2];
                bb[0] = __float_as_uint(Vs[(kc * 8 + t)     * VS_STRIDE + nt * 8 + g]);
                bb[1] = __float_as_uint(Vs[(kc * 8 + t + 4) * VS_STRIDE + nt * 8 + g]);
                mma8(o[nt], a, bb);
            }
        }
    }

    // Finalize
    float inv0 = 1.f / l0, inv1 = 1.f / l1;
    const size_t base = ((size_t)b * NN) * (HH * DHH) + h * DHH;
    const int r0 = i0 + g, r1 = i0 + g + 8;
    #pragma unroll
    for (int nt = 0; nt < 8; nt++) {
        float2 v0, v1;
        v0.x = o[nt][0] * inv0; v0.y = o[nt][1] * inv0;
        v1.x = o[nt][2] * inv1; v1.y = o[nt][3] * inv1;
        *(float2*)&g_att[base + (size_t)r0 * (HH * DHH) + nt * 8 + 2 * t] = v0;
        *(float2*)&g_att[base + (size_t)r1 * (HH * DHH) + nt * 8 + 2 * t] = v1;
    }
}

// ---------------------------------------------------------------------------
// Kernel 3: output projection, tf32 mma. Same structure as qkv_mma.
// ---------------------------------------------------------------------------
__global__ __launch_bounds__(256) void out_mma(
    const float* __restrict__ Wo,
    const float* __restrict__ bo,
    float* __restrict__ y)
{
    __shared__ float As[128 * AS_STRIDE];
    __shared__ float Bs[64 * BS_STRIDE];

    const int tid = threadIdx.x;
    const int w = tid >> 5, lane = tid & 31;
    const int g = lane >> 2, t = lane & 3;
    const int wm = w >> 1, wn = w & 1;

    const int rowBase = blockIdx.y * 128;
    const int colBase = blockIdx.x * 64;

    float acc[2][4][4] = {};

    for (int kt = 0; kt < DD; kt += 32) {
        __syncthreads();
        #pragma unroll
        for (int i = 0; i < 4; i++) {
            int f = tid + i * 256;
            int row = f >> 3, c4 = (f & 7) << 2;
            float4 av = *(const float4*)&g_att[(size_t)(rowBase + row) * DD + kt + c4];
            As[row * AS_STRIDE + c4 + 0] = f2tff(av.x);
            As[row * AS_STRIDE + c4 + 1] = f2tff(av.y);
            As[row * AS_STRIDE + c4 + 2] = f2tff(av.z);
            As[row * AS_STRIDE + c4 + 3] = f2tff(av.w);
        }
        #pragma unroll
        for (int i = 0; i < 8; i++) {
            int f = tid + i * 256;
            int k = f >> 6, n = f & 63;
            Bs[n * BS_STRIDE + k] = f2tff(Wo[(size_t)(kt + k) * DD + colBase + n]);
        }
        __syncthreads();

        #pragma unroll
        for (int ks = 0; ks < 4; ks++) {
            unsigned a[2][4];
            #pragma unroll
            for (int mi = 0; mi < 2; mi++) {
                int mb = wm * 32 + mi * 16;
                a[mi][0] = __float_as_uint(As[(mb + g)     * AS_STRIDE + ks * 8 + t]);
                a[mi][1] = __float_as_uint(As[(mb + g + 8) * AS_STRIDE + ks * 8 + t]);
                a[mi][2] = __float_as_uint(As[(mb + g)     * AS_STRIDE + ks * 8 + t + 4]);
                a[mi][3] = __float_as_uint(As[(mb + g + 8) * AS_STRIDE + ks * 8 + t + 4]);
            }
            #pragma unroll
            for (int ni = 0; ni < 4; ni++) {
                int n = wn * 32 + ni * 8 + g;
                unsigned bb[2];
                bb[0] = __float_as_uint(Bs[n * BS_STRIDE + ks * 8 + t]);
                bb[1] = __float_as_uint(Bs[n * BS_STRIDE + ks * 8 + t + 4]);
                mma8(acc[0][ni], a[0], bb);
                mma8(acc[1][ni], a[1], bb);
            }
        }
    }

    #pragma unroll
    for (int mi = 0; mi < 2; mi++) {
        #pragma unroll
        for (int ni = 0; ni < 4; ni++) {
            int gm0 = rowBase + wm * 32 + mi * 16 + g;
            int gn  = colBase + wn * 32 + ni * 8 + 2 * t;
            float2 bov = *(const float2*)&bo[gn];
            float2 v0; v0.x = acc[mi][ni][0] + bov.x; v0.y = acc[mi][ni][1] + bov.y;
            float2 v1; v1.x = acc[mi][ni][2] + bov.x; v1.y = acc[mi][ni][3] + bov.y;
            *(float2*)&y[(size_t)gm0 * DD + gn] = v0;
            *(float2*)&y[(size_t)(gm0 + 8) * DD + gn] = v1;
        }
    }
}

// ---------------------------------------------------------------------------
extern "C" void kernel_launch(void* const* d_in, const int* in_sizes, int n_in,
                              void* d_out, int out_size)
{
    const float* x       = (const float*)d_in[0];
    const float* Wq      = (const float*)d_in[1];
    const float* Wk      = (const float*)d_in[2];
    const float* Wv      = (const float*)d_in[3];
    const float* rel_pos = (const float*)d_in[4];
    const float* c_emb   = (const float*)d_in[5];
    const float* Wo      = (const float*)d_in[6];
    const float* bo      = (const float*)d_in[7];
    float* y             = (float*)d_out;

    dim3 gQKV(DD / 64, (BB * NN) / 128, 3);
    qkv_mma<<<gQKV, 256>>>(x, Wq, Wk, Wv);

    size_t attSmem = (size_t)ATT_SMEM_FLOATS * sizeof(float);
    cudaFuncSetAttribute(attention_mma,
                         cudaFuncAttributeMaxDynamicSharedMemorySize,
                         (int)attSmem);
    dim3 gAtt(NN / 128, HH, BB);
    attention_mma<<<gAtt, 256, attSmem>>>(rel_pos, c_emb);

    dim3 gOut(DD / 64, (BB * NN) / 128);
    out_mma<<<gOut, 256>>>(Wo, bo, y);
}